// round 1
// baseline (speedup 1.0000x reference)
#include <cuda_runtime.h>
#include <cstdint>

#define BATCH 32
#define NODES 1365         // nodes levels 0..5
#define NODES_ALL 5461     // nodes levels 0..6

static const long long TOK_ELEMS = (long long)BATCH * NODES_ALL * 192; // 33,552,384
static const long long MASK_OFF_ = TOK_ELEMS;
static const long long INFO_OFF_ = TOK_ELEMS + (long long)BATCH * NODES_ALL;

__device__ __constant__ int c_off[8] = {0, 1, 5, 21, 85, 341, 1365, 5461};

// ---- scratch (device globals; no allocations allowed) ----
__device__ float g_gray[BATCH * 512 * 512];          // 33.5 MB
__device__ float g_sum[BATCH * NODES];
__device__ float g_ssq[BATCH * NODES];
__device__ float g_edge[BATCH * NODES];
__device__ float g_epart[BATCH * 4 * 256];           // per-tile partial edge sums, levels 0..3
__device__ unsigned char g_split[BATCH * NODES];
__device__ unsigned char g_mask[BATCH * NODES_ALL];

// ============================================================
// K1: gray + level-5 (16x16 patch) sum / sumsq over 3 channels
// ============================================================
__global__ void k_gray_stats(const float* __restrict__ img) {
    int b = blockIdx.y;
    int tile = blockIdx.x;            // 0..1023, = ty*32+tx
    int ty = tile >> 5, tx = tile & 31;
    int t = threadIdx.x;              // 256
    int py = t >> 4, px = t & 15;
    int Y = ty * 16 + py, X = tx * 16 + px;
    size_t base = ((size_t)b * 3) * 262144 + (size_t)Y * 512 + X;
    float c0 = img[base];
    float c1 = img[base + 262144];
    float c2 = img[base + 524288];
    float s = c0 + c1 + c2;
    g_gray[(size_t)b * 262144 + (size_t)Y * 512 + X] = s * (1.0f / 3.0f);
    float ss = c0 * c0 + c1 * c1 + c2 * c2;

    __shared__ float rs[8], rq[8];
    #pragma unroll
    for (int o = 16; o; o >>= 1) {
        s  += __shfl_xor_sync(0xffffffffu, s,  o);
        ss += __shfl_xor_sync(0xffffffffu, ss, o);
    }
    int wid = t >> 5;
    if ((t & 31) == 0) { rs[wid] = s; rq[wid] = ss; }
    __syncthreads();
    if (t < 8) {
        s = rs[t]; ss = rq[t];
        #pragma unroll
        for (int o = 4; o; o >>= 1) {
            s  += __shfl_xor_sync(0xffu, s,  o);
            ss += __shfl_xor_sync(0xffu, ss, o);
        }
        if (t == 0) {
            int idx = b * NODES + 341 + tile;
            g_sum[idx] = s;
            g_ssq[idx] = ss;
        }
    }
}

// ============================================================
// K2: aggregate sums up the quadtree (levels 4..0), one CTA per b
// ============================================================
__global__ void k_aggregate() {
    int b = blockIdx.x;
    float* S = g_sum + (size_t)b * NODES;
    float* Q = g_ssq + (size_t)b * NODES;
    for (int l = 4; l >= 0; l--) {
        int n = 1 << l, nn = n << 1;
        int cb = c_off[l + 1], ob = c_off[l];
        for (int i = threadIdx.x; i < n * n; i += blockDim.x) {
            int r = i >> l, c = i & (n - 1);
            int k0 = cb + (2 * r) * nn + 2 * c;
            int k2 = k0 + nn;
            S[ob + i] = S[k0] + S[k0 + 1] + S[k2] + S[k2 + 1];
            Q[ob + i] = Q[k0] + Q[k0 + 1] + Q[k2] + Q[k2 + 1];
        }
        __syncthreads();
    }
}

// ============================================================
// K3: per-level Sobel edge sums. 32x32 tile per CTA (1024 thr).
// Levels 4,5 stored directly; levels 0..3 stored as per-tile partials.
// ============================================================
__global__ void k_edge() {
    int b = blockIdx.y;
    int ty = blockIdx.x >> 4, tx = blockIdx.x & 15;
    __shared__ float sg[34][36];
    __shared__ float swarp[32];
    __shared__ float s5[64];
    int t = threadIdx.x;
    const float* gr = g_gray + (size_t)b * 262144;
    int oy = ty * 32 - 1, ox = tx * 32 - 1;
    for (int i = t; i < 34 * 34; i += 1024) {
        int sy = i / 34, sx = i - sy * 34;
        int gy = oy + sy, gx = ox + sx;
        float v = 0.0f;
        if (gy >= 0 && gy < 512 && gx >= 0 && gx < 512) v = gr[gy * 512 + gx];
        sg[sy][sx] = v;
    }
    __syncthreads();
    int py = t >> 5, px = t & 31;
    int Y = ty * 32 + py, X = tx * 32 + px;
    float gNW = sg[py][px],     gN = sg[py][px + 1],     gNE = sg[py][px + 2];
    float gW  = sg[py + 1][px],                          gE  = sg[py + 1][px + 2];
    float gSW = sg[py + 2][px], gS = sg[py + 2][px + 1], gSE = sg[py + 2][px + 2];

    float mag[6];
    #pragma unroll
    for (int l = 0; l < 6; l++) {
        int hm = (512 >> l) - 1;
        float vt = (Y & hm) ? 1.0f : 0.0f;
        float vb = ((Y & hm) != hm) ? 1.0f : 0.0f;
        float vl = (X & hm) ? 1.0f : 0.0f;
        float vr = ((X & hm) != hm) ? 1.0f : 0.0f;
        float ex = vr * (vt * gNE + 2.0f * gE + vb * gSE)
                 - vl * (vt * gNW + 2.0f * gW + vb * gSW);
        float ey = vb * (vl * gSW + 2.0f * gS + vr * gSE)
                 - vt * (vl * gNW + 2.0f * gN + vr * gNE);
        mag[l] = sqrtf(ex * ex + ey * ey);
    }

    float* eb = g_edge + (size_t)b * NODES;
    #pragma unroll
    for (int l = 0; l < 5; l++) {
        float v = mag[l];
        #pragma unroll
        for (int o = 16; o; o >>= 1) v += __shfl_xor_sync(0xffffffffu, v, o);
        if (px == 0) swarp[py] = v;
        __syncthreads();
        if (t < 32) {
            float w = swarp[t];
            #pragma unroll
            for (int o = 16; o; o >>= 1) w += __shfl_xor_sync(0xffffffffu, w, o);
            if (t == 0) {
                if (l == 4) {
                    eb[c_off[4] + ty * 16 + tx] = w;
                } else {
                    g_epart[(b * 4 + l) * 256 + ty * 16 + tx] = w;
                }
            }
        }
        __syncthreads();
    }
    // level 5: four 16x16 quadrants of this tile
    {
        float v = mag[5];
        #pragma unroll
        for (int o = 8; o; o >>= 1) v += __shfl_xor_sync(0xffffffffu, v, o);
        if ((px & 15) == 0) s5[py * 2 + (px >> 4)] = v;
        __syncthreads();
        if (t < 4) {
            int qy = t >> 1, qx = t & 1;
            float w = 0.0f;
            #pragma unroll
            for (int r = 0; r < 16; r++) w += s5[(qy * 16 + r) * 2 + qx];
            eb[c_off[5] + (ty * 2 + qy) * 32 + (tx * 2 + qx)] = w;
        }
    }
}

// ============================================================
// K3b: deterministic reduce of per-tile partials into levels 0..3
// ============================================================
__global__ void k_edge_red() {
    int i = blockIdx.x * blockDim.x + threadIdx.x;
    if (i >= BATCH * 85) return;
    int b = i / 85, node = i - b * 85;
    int l = node < 1 ? 0 : node < 5 ? 1 : node < 21 ? 2 : 3;
    int base = c_off[l];
    int idx = node - base;
    int n = 1 << l;
    int r = idx >> l, c = idx & (n - 1);
    int sz = 16 >> l;
    float s = 0.0f;
    const float* ep = g_epart + (b * 4 + l) * 256;
    for (int dy = 0; dy < sz; dy++)
        for (int dx = 0; dx < sz; dx++)
            s += ep[(r * sz + dy) * 16 + (c * sz + dx)];
    g_edge[(size_t)b * NODES + node] = s;
}

// ============================================================
// K4: tiled MLP. 128 items per CTA, weights + activations in smem.
// split = (logit >= 0)  (sigmoid(x)>=0.5 <=> x>=0)
// ============================================================
#define MLP_ITEMS 128
#define MLP_SMEM_FLOATS 42240   // 168,960 bytes

__global__ void k_mlp(const float* __restrict__ W1, const float* __restrict__ b1,
                      const float* __restrict__ W2, const float* __restrict__ b2,
                      const float* __restrict__ W3, const float* __restrict__ b3,
                      const float* __restrict__ W4, const float* __restrict__ b4) {
    extern __shared__ float sm[];
    float* sW1 = sm;                 // 768
    float* sb1 = sW1 + 768;          // 128
    float* sW2 = sb1 + 128;          // 8192
    float* sb2 = sW2 + 8192;         // 64
    float* sW3 = sb2 + 64;           // 2048
    float* sb3 = sW3 + 2048;         // 32
    float* sW4 = sb3 + 32;           // 32
    float* sF  = sW4 + 32;           // 6*128  [feat][item]
    float* sH1 = sF + 768;           // 128*132
    float* sH2 = sH1 + 128 * 132;    // 128*68
    float* sH3 = sH2 + 128 * 68;     // 128*36

    int t = threadIdx.x;  // 256
    for (int i = t; i < 768; i += 256) sW1[i] = W1[i];
    for (int i = t; i < 128; i += 256) sb1[i] = b1[i];
    for (int i = t; i < 8192; i += 256) sW2[i] = W2[i];
    if (t < 64) sb2[t] = b2[t];
    for (int i = t; i < 2048; i += 256) sW3[i] = W3[i];
    if (t < 32) { sb3[t] = b3[t]; sW4[t] = W4[t]; }
    float bias4 = b4[0];
    int base = blockIdx.x * MLP_ITEMS;

    // phase 1: features
    if (t < 128) {
        int item = base + t;
        float f0 = 0, f1 = 0, fv = 0, fm = 0, fe = 0;
        if (item < BATCH * NODES) {
            int node = item % NODES;
            int l = node < 1 ? 0 : node < 5 ? 1 : node < 21 ? 2 : node < 85 ? 3 : node < 341 ? 4 : 5;
            int hl = 512 >> l;
            float N = 3.0f * (float)hl * (float)hl;
            float s = g_sum[item], q = g_ssq[item], e = g_edge[item];
            float mean = s / N;
            float var = (q - s * mean) / (N - 1.0f);
            float edge = e / ((float)hl * (float)hl);
            f0 = (float)l; f1 = (float)hl; fv = var; fm = mean; fe = edge;
        }
        sF[0 * 128 + t] = f0;
        sF[1 * 128 + t] = f1;
        sF[2 * 128 + t] = f1;
        sF[3 * 128 + t] = fv;
        sF[4 * 128 + t] = fm;
        sF[5 * 128 + t] = fe;
    }
    __syncthreads();

    // phase 2: H1 = relu(F @ W1 + b1)   thread: 1 item-half (64 outputs)
    {
        int it = t >> 1;
        int j0 = (t & 1) * 64;
        float f[6];
        #pragma unroll
        for (int i = 0; i < 6; i++) f[i] = sF[i * 128 + it];
        for (int j = j0; j < j0 + 64; j++) {
            float acc = sb1[j];
            #pragma unroll
            for (int i = 0; i < 6; i++) acc += f[i] * sW1[i * 128 + j];
            sH1[it * 132 + j] = fmaxf(acc, 0.0f);
        }
    }
    __syncthreads();

    // phase 3: H2 = relu(H1 @ W2 + b2)   thread: 4 items x 8 outputs
    {
        int it0 = (t >> 3) * 4;
        int j0 = (t & 7) * 8;
        float acc[4][8];
        #pragma unroll
        for (int m = 0; m < 4; m++)
            #pragma unroll
            for (int j = 0; j < 8; j++) acc[m][j] = sb2[j0 + j];
        for (int i = 0; i < 128; i += 4) {
            float a[4][4];
            #pragma unroll
            for (int m = 0; m < 4; m++) {
                float4 v = *(const float4*)&sH1[(it0 + m) * 132 + i];
                a[m][0] = v.x; a[m][1] = v.y; a[m][2] = v.z; a[m][3] = v.w;
            }
            #pragma unroll
            for (int k = 0; k < 4; k++) {
                float4 w0 = *(const float4*)&sW2[(i + k) * 64 + j0];
                float4 w1 = *(const float4*)&sW2[(i + k) * 64 + j0 + 4];
                float wv[8] = {w0.x, w0.y, w0.z, w0.w, w1.x, w1.y, w1.z, w1.w};
                #pragma unroll
                for (int m = 0; m < 4; m++)
                    #pragma unroll
                    for (int j = 0; j < 8; j++) acc[m][j] += a[m][k] * wv[j];
            }
        }
        #pragma unroll
        for (int m = 0; m < 4; m++)
            #pragma unroll
            for (int j = 0; j < 8; j++)
                sH2[(it0 + m) * 68 + j0 + j] = fmaxf(acc[m][j], 0.0f);
    }
    __syncthreads();

    // phase 4: H3 = relu(H2 @ W3 + b3)   thread: 2 items x 8 outputs
    {
        int it0 = (t >> 2) * 2;
        int j0 = (t & 3) * 8;
        float acc[2][8];
        #pragma unroll
        for (int m = 0; m < 2; m++)
            #pragma unroll
            for (int j = 0; j < 8; j++) acc[m][j] = sb3[j0 + j];
        for (int i = 0; i < 64; i += 4) {
            float a[2][4];
            #pragma unroll
            for (int m = 0; m < 2; m++) {
                float4 v = *(const float4*)&sH2[(it0 + m) * 68 + i];
                a[m][0] = v.x; a[m][1] = v.y; a[m][2] = v.z; a[m][3] = v.w;
            }
            #pragma unroll
            for (int k = 0; k < 4; k++) {
                float4 w0 = *(const float4*)&sW3[(i + k) * 32 + j0];
                float4 w1 = *(const float4*)&sW3[(i + k) * 32 + j0 + 4];
                float wv[8] = {w0.x, w0.y, w0.z, w0.w, w1.x, w1.y, w1.z, w1.w};
                #pragma unroll
                for (int m = 0; m < 2; m++)
                    #pragma unroll
                    for (int j = 0; j < 8; j++) acc[m][j] += a[m][k] * wv[j];
            }
        }
        #pragma unroll
        for (int m = 0; m < 2; m++)
            #pragma unroll
            for (int j = 0; j < 8; j++)
                sH3[(it0 + m) * 36 + j0 + j] = fmaxf(acc[m][j], 0.0f);
    }
    __syncthreads();

    // phase 5: logit sign
    if (t < 128) {
        int item = base + t;
        float acc = bias4;
        #pragma unroll
        for (int k = 0; k < 32; k += 4) {
            float4 h = *(const float4*)&sH3[t * 36 + k];
            float4 w = *(const float4*)&sW4[k];
            acc += h.x * w.x + h.y * w.y + h.z * w.z + h.w * w.w;
        }
        if (item < BATCH * NODES) g_split[item] = (unsigned char)(acc >= 0.0f);
    }
}

// ============================================================
// K5: alive/mask propagation, one CTA per batch image
// ============================================================
__global__ void k_masks() {
    int b = blockIdx.x;
    __shared__ unsigned char alive[4096], nxt[4096];
    int t = threadIdx.x;
    if (t == 0) alive[0] = 1;
    __syncthreads();
    const unsigned char* sp = g_split + (size_t)b * NODES;
    unsigned char* mk = g_mask + (size_t)b * NODES_ALL;
    for (int l = 0; l < 6; l++) {
        int n = 1 << l, cnt = n * n, off = c_off[l], nn = n << 1;
        for (int i = t; i < cnt; i += blockDim.x) {
            unsigned char a = alive[i];
            unsigned char s = sp[off + i];
            mk[off + i] = (unsigned char)(a & (s ^ 1));
            unsigned char ch = (unsigned char)(a & s);
            int r = i >> l, c = i & (n - 1);
            int k0 = (2 * r) * nn + 2 * c;
            nxt[k0] = ch; nxt[k0 + 1] = ch; nxt[k0 + nn] = ch; nxt[k0 + nn + 1] = ch;
        }
        __syncthreads();
        for (int i = t; i < 4 * cnt; i += blockDim.x) alive[i] = nxt[i];
        __syncthreads();
    }
    for (int i = t; i < 4096; i += blockDim.x) mk[1365 + i] = alive[i];
}

// ============================================================
// K6: write tokens (Hilbert-DFS order), mask, level_info
// warp per (b, dfs position)
// ============================================================
__global__ void k_write(const float* __restrict__ img, float* __restrict__ out) {
    int gw = blockIdx.x * 8 + (threadIdx.x >> 5);
    if (gw >= BATCH * NODES_ALL) return;
    int lane = threadIdx.x & 31;
    int b = gw / NODES_ALL;
    int p = gw - b * NODES_ALL;

    // decode DFS position -> (level,row,col,path)
    int level = 0, row = 0, col = 0, pp = p, plen = 0;
    unsigned pathbits = 0;
    while (pp > 0) {
        pp--;
        int s = ((1 << (2 * (6 - level))) - 1) / 3;   // child subtree size
        int ci = pp / s;
        pp -= ci * s;
        int q = (0x3102 >> (ci * 4)) & 0xF;           // HILBERT = [2,0,1,3]
        row = 2 * row + (q >> 1);
        col = 2 * col + (q & 1);
        pathbits |= (unsigned)q << (3 * plen);
        plen++;
        level++;
    }
    int off = ((1 << (2 * level)) - 1) / 3;
    int node = off + (row << level) + col;
    float m = g_mask[(size_t)b * NODES_ALL + node] ? 1.0f : 0.0f;
    int hl = 512 >> level;
    int Y0 = row * hl + ((hl - 8) >> 1);
    int X0 = col * hl + ((hl - 8) >> 1);

    float* o = out + (size_t)gw * 192;
    if (lane < 24) {
        int c = lane >> 3, r = lane & 7;
        const float* src = img + ((size_t)(b * 3 + c) * 512 + (size_t)(Y0 + r)) * 512 + X0;
        float4 v0 = __ldg((const float4*)src);
        float4 v1 = __ldg((const float4*)(src + 4));
        v0.x *= m; v0.y *= m; v0.z *= m; v0.w *= m;
        v1.x *= m; v1.y *= m; v1.z *= m; v1.w *= m;
        float* dst = o + c * 64 + r * 8;
        *(float4*)dst = v0;
        *(float4*)(dst + 4) = v1;
    } else if (lane == 24) {
        out[MASK_OFF_ + (size_t)gw] = m;
    }
    if (b == 0 && lane < 16) {
        float v = 0.0f;
        if (lane == 0) v = (float)level;
        else if (lane - 1 < plen) v = (float)((pathbits >> (3 * (lane - 1))) & 7);
        out[INFO_OFF_ + (size_t)p * 16 + lane] = v;
    }
}

// ============================================================
extern "C" void kernel_launch(void* const* d_in, const int* in_sizes, int n_in,
                              void* d_out, int out_size) {
    const float* img = (const float*)d_in[0];
    const float* W1 = (const float*)d_in[1];
    const float* b1 = (const float*)d_in[2];
    const float* W2 = (const float*)d_in[3];
    const float* b2 = (const float*)d_in[4];
    const float* W3 = (const float*)d_in[5];
    const float* b3 = (const float*)d_in[6];
    const float* W4 = (const float*)d_in[7];
    const float* b4 = (const float*)d_in[8];
    float* out = (float*)d_out;

    cudaFuncSetAttribute(k_mlp, cudaFuncAttributeMaxDynamicSharedMemorySize,
                         MLP_SMEM_FLOATS * (int)sizeof(float));

    k_gray_stats<<<dim3(1024, BATCH), 256>>>(img);
    k_aggregate<<<BATCH, 256>>>();
    k_edge<<<dim3(256, BATCH), 1024>>>();
    k_edge_red<<<(BATCH * 85 + 255) / 256, 256>>>();
    int mlp_blocks = (BATCH * NODES + MLP_ITEMS - 1) / MLP_ITEMS;  // 342
    k_mlp<<<mlp_blocks, 256, MLP_SMEM_FLOATS * sizeof(float)>>>(W1, b1, W2, b2, W3, b3, W4, b4);
    k_masks<<<BATCH, 256>>>();
    k_write<<<(BATCH * NODES_ALL + 7) / 8, 256>>>(img, out);
}

// round 3
// speedup vs baseline: 1.1043x; 1.1043x over previous
#include <cuda_runtime.h>
#include <cstdint>

#define BATCH 32
#define NODES 1365         // nodes levels 0..5
#define NODES_ALL 5461     // nodes levels 0..6

static const long long TOK_ELEMS = (long long)BATCH * NODES_ALL * 192; // 33,552,384
static const long long MASK_OFF_ = TOK_ELEMS;
static const long long INFO_OFF_ = TOK_ELEMS + (long long)BATCH * NODES_ALL;

__device__ __constant__ int c_off[8] = {0, 1, 5, 21, 85, 341, 1365, 5461};

// ---- scratch (device globals; no allocations allowed) ----
__device__ float g_sum[BATCH * NODES];
__device__ float g_ssq[BATCH * NODES];
__device__ float g_edge[BATCH * NODES];
__device__ float g_epart[BATCH * 4 * 256];           // per-tile partial edge sums, levels 0..3
__device__ unsigned char g_split[BATCH * NODES];
__device__ unsigned char g_mask[BATCH * NODES_ALL];

// ============================================================
// K1: fused gray + level-5 stats + per-level Sobel edge sums.
// One CTA = one 32x32 pixel tile (1024 threads), gray never hits HBM.
// ============================================================
__global__ void k_gray_edge(const float* __restrict__ img) {
    int b = blockIdx.y;
    int ty = blockIdx.x >> 4, tx = blockIdx.x & 15;
    __shared__ float sg[34][36];
    __shared__ float swarp[32];
    __shared__ float s5[64];
    __shared__ float sh_s[64], sh_q[64];   // stats: [row][half]
    int t = threadIdx.x;
    int py = t >> 5, px = t & 31;
    int Y = ty * 32 + py, X = tx * 32 + px;

    const float* ib = img + (size_t)b * 3 * 262144;
    size_t pidx = (size_t)Y * 512 + X;
    float c0 = ib[pidx];
    float c1 = ib[pidx + 262144];
    float c2 = ib[pidx + 524288];
    float s  = c0 + c1 + c2;
    float ss = c0 * c0 + c1 * c1 + c2 * c2;
    sg[py + 1][px + 1] = s * (1.0f / 3.0f);

    // halo: 132 perimeter pixels of the 34x34 window
    if (t < 132) {
        int sy, sx;
        if (t < 34)       { sy = 0;          sx = t; }
        else if (t < 68)  { sy = 33;         sx = t - 34; }
        else if (t < 100) { sy = t - 68 + 1; sx = 0; }
        else              { sy = t - 100 + 1; sx = 33; }
        int gy = ty * 32 - 1 + sy, gx = tx * 32 - 1 + sx;
        float v = 0.0f;
        if (gy >= 0 && gy < 512 && gx >= 0 && gx < 512) {
            size_t q = (size_t)gy * 512 + gx;
            v = (ib[q] + ib[q + 262144] + ib[q + 524288]) * (1.0f / 3.0f);
        }
        sg[sy][sx] = v;
    }
    __syncthreads();

    // Sobel neighborhood (sg origin is at (-1,-1) of the tile)
    float gNW = sg[py][px],     gN = sg[py][px + 1],     gNE = sg[py][px + 2];
    float gW  = sg[py + 1][px],                          gE  = sg[py + 1][px + 2];
    float gSW = sg[py + 2][px], gS = sg[py + 2][px + 1], gSE = sg[py + 2][px + 2];

    float mag[6];
    #pragma unroll
    for (int l = 0; l < 6; l++) {
        int hm = (512 >> l) - 1;
        float vt = (Y & hm) ? 1.0f : 0.0f;
        float vb = ((Y & hm) != hm) ? 1.0f : 0.0f;
        float vl = (X & hm) ? 1.0f : 0.0f;
        float vr = ((X & hm) != hm) ? 1.0f : 0.0f;
        float ex = vr * (vt * gNE + 2.0f * gE + vb * gSE)
                 - vl * (vt * gNW + 2.0f * gW + vb * gSW);
        float ey = vb * (vl * gSW + 2.0f * gS + vr * gSE)
                 - vt * (vl * gNW + 2.0f * gN + vr * gNE);
        mag[l] = sqrtf(ex * ex + ey * ey);
    }

    // --- stats: reduce s/ss per 16x16 quadrant (half-warp shfl, then rows)
    #pragma unroll
    for (int o = 8; o; o >>= 1) {
        s  += __shfl_xor_sync(0xffffffffu, s,  o);
        ss += __shfl_xor_sync(0xffffffffu, ss, o);
    }
    if ((px & 15) == 0) {
        int h = px >> 4;
        sh_s[(py << 1) | h] = s;
        sh_q[(py << 1) | h] = ss;
    }
    __syncthreads();
    if (t < 4) {
        int qy = t >> 1, qx = t & 1;
        float as = 0.0f, aq = 0.0f;
        #pragma unroll
        for (int r = 0; r < 16; r++) {
            as += sh_s[(qy * 16 + r) * 2 + qx];
            aq += sh_q[(qy * 16 + r) * 2 + qx];
        }
        int leaf = (ty * 2 + qy) * 32 + (tx * 2 + qx);
        g_sum[b * NODES + 341 + leaf] = as;
        g_ssq[b * NODES + 341 + leaf] = aq;
    }

    // --- edge reductions
    float* eb = g_edge + (size_t)b * NODES;
    #pragma unroll
    for (int l = 0; l < 5; l++) {
        float v = mag[l];
        #pragma unroll
        for (int o = 16; o; o >>= 1) v += __shfl_xor_sync(0xffffffffu, v, o);
        if (px == 0) swarp[py] = v;
        __syncthreads();
        if (t < 32) {
            float w = swarp[t];
            #pragma unroll
            for (int o = 16; o; o >>= 1) w += __shfl_xor_sync(0xffffffffu, w, o);
            if (t == 0) {
                if (l == 4) eb[85 + ty * 16 + tx] = w;
                else        g_epart[(b * 4 + l) * 256 + ty * 16 + tx] = w;
            }
        }
        __syncthreads();
    }
    // level 5: four 16x16 quadrants of this tile
    {
        float v = mag[5];
        #pragma unroll
        for (int o = 8; o; o >>= 1) v += __shfl_xor_sync(0xffffffffu, v, o);
        if ((px & 15) == 0) s5[py * 2 + (px >> 4)] = v;
        __syncthreads();
        if (t < 4) {
            int qy = t >> 1, qx = t & 1;
            float w = 0.0f;
            #pragma unroll
            for (int r = 0; r < 16; r++) w += s5[(qy * 16 + r) * 2 + qx];
            eb[341 + (ty * 2 + qy) * 32 + (tx * 2 + qx)] = w;
        }
    }
}

// ============================================================
// K2: per-batch tree aggregation of sums + edge partial reduce.
// One CTA per batch image.
// ============================================================
__global__ void k_aggregate() {
    int b = blockIdx.x;
    int t = threadIdx.x;  // 256
    __shared__ float sp[256];

    // edge levels 0..3 from per-tile partials
    #pragma unroll
    for (int l = 0; l < 4; l++) {
        sp[t] = g_epart[(b * 4 + l) * 256 + t];
        __syncthreads();
        int n = 1 << l, P = 16 >> l;
        if (t < n * n) {
            int r = t >> l, c = t & (n - 1);
            float acc = 0.0f;
            for (int dy = 0; dy < P; dy++)
                for (int dx = 0; dx < P; dx++)
                    acc += sp[(r * P + dy) * 16 + (c * P + dx)];
            g_edge[(size_t)b * NODES + c_off[l] + t] = acc;
        }
        __syncthreads();
    }

    // sum/ssq quadtree aggregation, levels 4..0
    float* S = g_sum + (size_t)b * NODES;
    float* Q = g_ssq + (size_t)b * NODES;
    for (int l = 4; l >= 0; l--) {
        int n = 1 << l, nn = n << 1;
        int cb = c_off[l + 1], ob = c_off[l];
        for (int i = t; i < n * n; i += blockDim.x) {
            int r = i >> l, c = i & (n - 1);
            int k0 = cb + (2 * r) * nn + 2 * c;
            int k2 = k0 + nn;
            S[ob + i] = S[k0] + S[k0 + 1] + S[k2] + S[k2 + 1];
            Q[ob + i] = Q[k0] + Q[k0 + 1] + Q[k2] + Q[k2 + 1];
        }
        __syncthreads();
    }
}

// ============================================================
// K3: tiled MLP. 128 items per CTA, weights + activations in smem.
// split = (logit >= 0)  (sigmoid(x)>=0.5 <=> x>=0)
// ============================================================
#define MLP_ITEMS 128
#define MLP_SMEM_FLOATS 42240   // 168,960 bytes

__global__ void k_mlp(const float* __restrict__ W1, const float* __restrict__ b1,
                      const float* __restrict__ W2, const float* __restrict__ b2,
                      const float* __restrict__ W3, const float* __restrict__ b3,
                      const float* __restrict__ W4, const float* __restrict__ b4) {
    extern __shared__ float sm[];
    float* sW1 = sm;                 // 768
    float* sb1 = sW1 + 768;          // 128
    float* sW2 = sb1 + 128;          // 8192
    float* sb2 = sW2 + 8192;         // 64
    float* sW3 = sb2 + 64;           // 2048
    float* sb3 = sW3 + 2048;         // 32
    float* sW4 = sb3 + 32;           // 32
    float* sF  = sW4 + 32;           // 6*128  [feat][item]
    float* sH1 = sF + 768;           // 128*132
    float* sH2 = sH1 + 128 * 132;    // 128*68
    float* sH3 = sH2 + 128 * 68;     // 128*36

    int t = threadIdx.x;  // 256
    for (int i = t; i < 768; i += 256) sW1[i] = W1[i];
    for (int i = t; i < 128; i += 256) sb1[i] = b1[i];
    for (int i = t; i < 8192; i += 256) sW2[i] = W2[i];
    if (t < 64) sb2[t] = b2[t];
    for (int i = t; i < 2048; i += 256) sW3[i] = W3[i];
    if (t < 32) { sb3[t] = b3[t]; sW4[t] = W4[t]; }
    float bias4 = b4[0];
    int base = blockIdx.x * MLP_ITEMS;

    // phase 1: features
    if (t < 128) {
        int item = base + t;
        float f0 = 0, f1 = 0, fv = 0, fm = 0, fe = 0;
        if (item < BATCH * NODES) {
            int node = item % NODES;
            int l = node < 1 ? 0 : node < 5 ? 1 : node < 21 ? 2 : node < 85 ? 3 : node < 341 ? 4 : 5;
            int hl = 512 >> l;
            float N = 3.0f * (float)hl * (float)hl;
            float s = g_sum[item], q = g_ssq[item], e = g_edge[item];
            float mean = s / N;
            float var = (q - s * mean) / (N - 1.0f);
            float edge = e / ((float)hl * (float)hl);
            f0 = (float)l; f1 = (float)hl; fv = var; fm = mean; fe = edge;
        }
        sF[0 * 128 + t] = f0;
        sF[1 * 128 + t] = f1;
        sF[2 * 128 + t] = f1;
        sF[3 * 128 + t] = fv;
        sF[4 * 128 + t] = fm;
        sF[5 * 128 + t] = fe;
    }
    __syncthreads();

    // phase 2: H1 = relu(F @ W1 + b1)
    {
        int it = t >> 1;
        int j0 = (t & 1) * 64;
        float f[6];
        #pragma unroll
        for (int i = 0; i < 6; i++) f[i] = sF[i * 128 + it];
        for (int j = j0; j < j0 + 64; j++) {
            float acc = sb1[j];
            #pragma unroll
            for (int i = 0; i < 6; i++) acc += f[i] * sW1[i * 128 + j];
            sH1[it * 132 + j] = fmaxf(acc, 0.0f);
        }
    }
    __syncthreads();

    // phase 3: H2 = relu(H1 @ W2 + b2)
    {
        int it0 = (t >> 3) * 4;
        int j0 = (t & 7) * 8;
        float acc[4][8];
        #pragma unroll
        for (int m = 0; m < 4; m++)
            #pragma unroll
            for (int j = 0; j < 8; j++) acc[m][j] = sb2[j0 + j];
        for (int i = 0; i < 128; i += 4) {
            float a[4][4];
            #pragma unroll
            for (int m = 0; m < 4; m++) {
                float4 v = *(const float4*)&sH1[(it0 + m) * 132 + i];
                a[m][0] = v.x; a[m][1] = v.y; a[m][2] = v.z; a[m][3] = v.w;
            }
            #pragma unroll
            for (int k = 0; k < 4; k++) {
                float4 w0 = *(const float4*)&sW2[(i + k) * 64 + j0];
                float4 w1 = *(const float4*)&sW2[(i + k) * 64 + j0 + 4];
                float wv[8] = {w0.x, w0.y, w0.z, w0.w, w1.x, w1.y, w1.z, w1.w};
                #pragma unroll
                for (int m = 0; m < 4; m++)
                    #pragma unroll
                    for (int j = 0; j < 8; j++) acc[m][j] += a[m][k] * wv[j];
            }
        }
        #pragma unroll
        for (int m = 0; m < 4; m++)
            #pragma unroll
            for (int j = 0; j < 8; j++)
                sH2[(it0 + m) * 68 + j0 + j] = fmaxf(acc[m][j], 0.0f);
    }
    __syncthreads();

    // phase 4: H3 = relu(H2 @ W3 + b3)
    {
        int it0 = (t >> 2) * 2;
        int j0 = (t & 3) * 8;
        float acc[2][8];
        #pragma unroll
        for (int m = 0; m < 2; m++)
            #pragma unroll
            for (int j = 0; j < 8; j++) acc[m][j] = sb3[j0 + j];
        for (int i = 0; i < 64; i += 4) {
            float a[2][4];
            #pragma unroll
            for (int m = 0; m < 2; m++) {
                float4 v = *(const float4*)&sH2[(it0 + m) * 68 + i];
                a[m][0] = v.x; a[m][1] = v.y; a[m][2] = v.z; a[m][3] = v.w;
            }
            #pragma unroll
            for (int k = 0; k < 4; k++) {
                float4 w0 = *(const float4*)&sW3[(i + k) * 32 + j0];
                float4 w1 = *(const float4*)&sW3[(i + k) * 32 + j0 + 4];
                float wv[8] = {w0.x, w0.y, w0.z, w0.w, w1.x, w1.y, w1.z, w1.w};
                #pragma unroll
                for (int m = 0; m < 2; m++)
                    #pragma unroll
                    for (int j = 0; j < 8; j++) acc[m][j] += a[m][k] * wv[j];
            }
        }
        #pragma unroll
        for (int m = 0; m < 2; m++)
            #pragma unroll
            for (int j = 0; j < 8; j++)
                sH3[(it0 + m) * 36 + j0 + j] = fmaxf(acc[m][j], 0.0f);
    }
    __syncthreads();

    // phase 5: logit sign
    if (t < 128) {
        int item = base + t;
        float acc = bias4;
        #pragma unroll
        for (int k = 0; k < 32; k += 4) {
            float4 h = *(const float4*)&sH3[t * 36 + k];
            float4 w = *(const float4*)&sW4[k];
            acc += h.x * w.x + h.y * w.y + h.z * w.z + h.w * w.w;
        }
        if (item < BATCH * NODES) g_split[item] = (unsigned char)(acc >= 0.0f);
    }
}

// ============================================================
// K4: alive/mask propagation, one CTA per batch image
// ============================================================
__global__ void k_masks() {
    int b = blockIdx.x;
    __shared__ unsigned char alive[4096], nxt[4096];
    int t = threadIdx.x;
    if (t == 0) alive[0] = 1;
    __syncthreads();
    const unsigned char* sp = g_split + (size_t)b * NODES;
    unsigned char* mk = g_mask + (size_t)b * NODES_ALL;
    for (int l = 0; l < 6; l++) {
        int n = 1 << l, cnt = n * n, off = c_off[l], nn = n << 1;
        for (int i = t; i < cnt; i += blockDim.x) {
            unsigned char a = alive[i];
            unsigned char s = sp[off + i];
            mk[off + i] = (unsigned char)(a & (s ^ 1));
            unsigned char ch = (unsigned char)(a & s);
            int r = i >> l, c = i & (n - 1);
            int k0 = (2 * r) * nn + 2 * c;
            nxt[k0] = ch; nxt[k0 + 1] = ch; nxt[k0 + nn] = ch; nxt[k0 + nn + 1] = ch;
        }
        __syncthreads();
        for (int i = t; i < 4 * cnt; i += blockDim.x) alive[i] = nxt[i];
        __syncthreads();
    }
    for (int i = t; i < 4096; i += blockDim.x) mk[1365 + i] = alive[i];
}

// ============================================================
// K5: write tokens (Hilbert-DFS order), mask, level_info.
// Masked-out tokens are exact zeros -> skip the image read entirely.
// ============================================================
__global__ void k_write(const float* __restrict__ img, float* __restrict__ out) {
    int gw = blockIdx.x * 8 + (threadIdx.x >> 5);
    if (gw >= BATCH * NODES_ALL) return;
    int lane = threadIdx.x & 31;
    int b = gw / NODES_ALL;
    int p = gw - b * NODES_ALL;

    // decode DFS position -> (level,row,col,path)
    int level = 0, row = 0, col = 0, pp = p, plen = 0;
    unsigned pathbits = 0;
    while (pp > 0) {
        pp--;
        int s = ((1 << (2 * (6 - level))) - 1) / 3;   // child subtree size
        int ci = pp / s;
        pp -= ci * s;
        int q = (0x3102 >> (ci * 4)) & 0xF;           // HILBERT = [2,0,1,3]
        row = 2 * row + (q >> 1);
        col = 2 * col + (q & 1);
        pathbits |= (unsigned)q << (3 * plen);
        plen++;
        level++;
    }
    int off = ((1 << (2 * level)) - 1) / 3;
    int node = off + (row << level) + col;
    float m = g_mask[(size_t)b * NODES_ALL + node] ? 1.0f : 0.0f;

    float* o = out + (size_t)gw * 192;
    if (m != 0.0f) {
        int hl = 512 >> level;
        int Y0 = row * hl + ((hl - 8) >> 1);
        int X0 = col * hl + ((hl - 8) >> 1);
        if (lane < 24) {
            int c = lane >> 3, r = lane & 7;
            const float* src = img + ((size_t)(b * 3 + c) * 512 + (size_t)(Y0 + r)) * 512 + X0;
            float4 v0 = __ldg((const float4*)src);
            float4 v1 = __ldg((const float4*)(src + 4));
            float* dst = o + c * 64 + r * 8;
            *(float4*)dst = v0;
            *(float4*)(dst + 4) = v1;
        }
    } else {
        float4 z = make_float4(0.0f, 0.0f, 0.0f, 0.0f);
        if (lane < 24) {
            float* dst = o + lane * 8;
            *(float4*)dst = z;
            *(float4*)(dst + 4) = z;
        }
    }
    if (lane == 24) out[MASK_OFF_ + (size_t)gw] = m;
    if (b == 0 && lane >= 25 && lane < 27) {
        // lanes 25,26 write 8 info slots each (16 total)
        int base16 = (lane - 25) * 8;
        #pragma unroll
        for (int k = 0; k < 8; k++) {
            int slot = base16 + k;
            float v = 0.0f;
            if (slot == 0) v = (float)level;
            else if (slot - 1 < plen) v = (float)((pathbits >> (3 * (slot - 1))) & 7);
            out[INFO_OFF_ + (size_t)p * 16 + slot] = v;
        }
    }
}

// ============================================================
extern "C" void kernel_launch(void* const* d_in, const int* in_sizes, int n_in,
                              void* d_out, int out_size) {
    const float* img = (const float*)d_in[0];
    const float* W1 = (const float*)d_in[1];
    const float* b1 = (const float*)d_in[2];
    const float* W2 = (const float*)d_in[3];
    const float* b2 = (const float*)d_in[4];
    const float* W3 = (const float*)d_in[5];
    const float* b3 = (const float*)d_in[6];
    const float* W4 = (const float*)d_in[7];
    const float* b4 = (const float*)d_in[8];
    float* out = (float*)d_out;

    cudaFuncSetAttribute(k_mlp, cudaFuncAttributeMaxDynamicSharedMemorySize,
                         MLP_SMEM_FLOATS * (int)sizeof(float));

    k_gray_edge<<<dim3(256, BATCH), 1024>>>(img);
    k_aggregate<<<BATCH, 256>>>();
    int mlp_blocks = (BATCH * NODES + MLP_ITEMS - 1) / MLP_ITEMS;  // 342
    k_mlp<<<mlp_blocks, 256, MLP_SMEM_FLOATS * sizeof(float)>>>(W1, b1, W2, b2, W3, b3, W4, b4);
    k_masks<<<BATCH, 256>>>();
    k_write<<<(BATCH * NODES_ALL + 7) / 8, 256>>>(img, out);
}